// round 3
// baseline (speedup 1.0000x reference)
#include <cuda_runtime.h>
#include <cuda_bf16.h>

// ---------------------------------------------------------------------------
// GCN forward: h1 = relu(conv(x,W1,b1)); h2 = conv(h1,W2,b2);
// pooled = segment_mean(h2, batch); out = log_softmax(pooled@Wl + bl)
// conv(x,W,b) = dinv ⊙ (Adj_csr · (dinv ⊙ (x@W))) + b   (Adj includes self loops)
// Index dtype (int32 vs int64) detected at runtime on-device.
// ---------------------------------------------------------------------------

#define MAXN 100000
#define MAXE 640000
#define MAXCSR (MAXN + MAXE)
#define NGRAPH 64
#define HDIM 128

__device__ __align__(16) float d_bufA[MAXN * HDIM];
__device__ __align__(16) float d_bufB[MAXN * HDIM];
__device__ __align__(16) float d_pool[NGRAPH * HDIM];
__device__ int   d_cnt[MAXN];
__device__ int   d_incl[MAXN];
__device__ int   d_bsum[128];
__device__ int   d_rowptr[MAXN + 1];
__device__ int   d_fill[MAXN];
__device__ int   d_csr[MAXCSR];
__device__ float d_dinv[MAXN];
__device__ int   d_is64;

// ---------------- dtype detection ----------------

__global__ void k_detect(const unsigned int* __restrict__ w, int nwords) {
    __shared__ unsigned long long ssum;
    if (threadIdx.x == 0) ssum = 0;
    __syncthreads();
    unsigned long long local = 0;
    for (int i = 1 + 2 * threadIdx.x; i < nwords; i += 2 * blockDim.x) local += w[i];
    atomicAdd(&ssum, local);
    __syncthreads();
    if (threadIdx.x == 0) d_is64 = (ssum == 0ULL) ? 1 : 0;
}

__device__ __forceinline__ int loadIdx(const void* p, int i) {
    return d_is64 ? (int)((const long long*)p)[i] : ((const int*)p)[i];
}

// ---------------- degree / CSR construction ----------------

__global__ void k_init(int N) {
    int i = blockIdx.x * blockDim.x + threadIdx.x;
    if (i < N) { d_cnt[i] = 1; d_fill[i] = 0; }   // cnt=1 for self loop
}

__global__ void k_count(const void* __restrict__ ei, int E) {
    int e = blockIdx.x * blockDim.x + threadIdx.x;
    if (e < E) atomicAdd(&d_cnt[loadIdx(ei, E + e)], 1);   // dst row
}

__global__ void k_scan1(int N) {
    __shared__ int s[1024];
    int i = blockIdx.x * 1024 + threadIdx.x;
    int v = (i < N) ? d_cnt[i] : 0;
    if (i < N) d_dinv[i] = rsqrtf((float)v);
    s[threadIdx.x] = v;
    __syncthreads();
    for (int off = 1; off < 1024; off <<= 1) {
        int t = (threadIdx.x >= off) ? s[threadIdx.x - off] : 0;
        __syncthreads();
        s[threadIdx.x] += t;
        __syncthreads();
    }
    if (i < N) d_incl[i] = s[threadIdx.x];
    if (threadIdx.x == 1023) d_bsum[blockIdx.x] = s[1023];
}

__global__ void k_scan2(int nb, int N) {
    if (threadIdx.x == 0 && blockIdx.x == 0) {
        int run = 0;
        for (int b = 0; b < nb; b++) { int t = d_bsum[b]; d_bsum[b] = run; run += t; }
        d_rowptr[N] = run;
    }
}

__global__ void k_scan3(int N) {
    int i = blockIdx.x * blockDim.x + threadIdx.x;
    if (i < N) d_rowptr[i] = d_incl[i] - d_cnt[i] + d_bsum[i >> 10];
}

__global__ void k_csrfill(const void* __restrict__ ei, int E, int N) {
    int id = blockIdx.x * blockDim.x + threadIdx.x;
    if (id >= E + N) return;
    int s, dn;
    if (id < E) { s = loadIdx(ei, id); dn = loadIdx(ei, E + id); }
    else        { s = dn = id - E; }                     // self loop
    int pos = d_rowptr[dn] + atomicAdd(&d_fill[dn], 1);
    d_csr[pos] = s;
}

// ---------------- GEMM: out[row] = dinv[row] * (A[row] @ W) ----------------

__global__ void __launch_bounds__(256) k_gemm(const float* __restrict__ Ain,
                                              int srcSel,
                                              const float* __restrict__ W,
                                              int N) {
    const float* A = (srcSel == 0) ? Ain : (const float*)d_bufB;
    float* out = d_bufA;

    __shared__ __align__(16) float As[128][68];   // transposed: As[k][r]
    int tid  = threadIdx.x;
    int row0 = blockIdx.x * 64;

    for (int idx = tid; idx < 64 * 128; idx += 256) {
        int r = idx >> 7, k = idx & 127;
        int row = row0 + r;
        As[k][r] = (row < N) ? A[row * 128 + k] : 0.f;
    }
    __syncthreads();

    int tx = tid & 15, ty = tid >> 4;      // cols tx*8..+7, rows ty*4..+3
    float acc[4][8];
#pragma unroll
    for (int i = 0; i < 4; i++)
#pragma unroll
        for (int j = 0; j < 8; j++) acc[i][j] = 0.f;

    const float* Wp = W + tx * 8;
#pragma unroll 8
    for (int k = 0; k < 128; k++) {
        float4 a  = *(const float4*)&As[k][ty * 4];
        float4 w0 = __ldg((const float4*)(Wp + k * 128));
        float4 w1 = __ldg((const float4*)(Wp + k * 128 + 4));
        float av[4] = {a.x, a.y, a.z, a.w};
        float wv[8] = {w0.x, w0.y, w0.z, w0.w, w1.x, w1.y, w1.z, w1.w};
#pragma unroll
        for (int i = 0; i < 4; i++)
#pragma unroll
            for (int j = 0; j < 8; j++) acc[i][j] += av[i] * wv[j];
    }

#pragma unroll
    for (int i = 0; i < 4; i++) {
        int row = row0 + ty * 4 + i;
        if (row < N) {
            float dd = d_dinv[row];
            float4 o0 = make_float4(acc[i][0]*dd, acc[i][1]*dd, acc[i][2]*dd, acc[i][3]*dd);
            float4 o1 = make_float4(acc[i][4]*dd, acc[i][5]*dd, acc[i][6]*dd, acc[i][7]*dd);
            *(float4*)&out[row * 128 + tx * 8]     = o0;
            *(float4*)&out[row * 128 + tx * 8 + 4] = o1;
        }
    }
}

// ---------------- Aggregation: warp per node ----------------

template <bool RELU>
__global__ void k_agg(const float* __restrict__ bias, int N) {
    int w    = (blockIdx.x * blockDim.x + threadIdx.x) >> 5;
    int lane = threadIdx.x & 31;
    if (w >= N) return;
    int rs = d_rowptr[w], re = d_rowptr[w + 1];
    const float4* in4 = (const float4*)d_bufA;
    float4 acc = make_float4(0.f, 0.f, 0.f, 0.f);
    for (int e = rs; e < re; e++) {
        int s = d_csr[e];
        float4 v = __ldg(&in4[s * 32 + lane]);
        acc.x += v.x; acc.y += v.y; acc.z += v.z; acc.w += v.w;
    }
    float dd = d_dinv[w];
    float4 b = __ldg(&((const float4*)bias)[lane]);
    float4 o = make_float4(acc.x * dd + b.x, acc.y * dd + b.y,
                           acc.z * dd + b.z, acc.w * dd + b.w);
    if (RELU) {
        o.x = fmaxf(o.x, 0.f); o.y = fmaxf(o.y, 0.f);
        o.z = fmaxf(o.z, 0.f); o.w = fmaxf(o.w, 0.f);
    }
    ((float4*)d_bufB)[w * 32 + lane] = o;
}

// ---------------- Mean pool per graph (batch sorted) ----------------

__global__ void k_pool(const void* __restrict__ batch, int N) {
    int g = blockIdx.x;        // 0..63
    int c = threadIdx.x;       // 0..127
    int lo = 0, hi = N;
    while (lo < hi) { int mid = (lo + hi) >> 1; if (loadIdx(batch, mid) < g) lo = mid + 1; else hi = mid; }
    int s = lo;
    lo = s; hi = N;
    while (lo < hi) { int mid = (lo + hi) >> 1; if (loadIdx(batch, mid) < g + 1) lo = mid + 1; else hi = mid; }
    int e = lo;
    float sum = 0.f;
    for (int i = s; i < e; i++) sum += d_bufB[i * 128 + c];
    float cnt = (float)((e - s) > 0 ? (e - s) : 1);
    d_pool[g * 128 + c] = sum / cnt;
}

// ---------------- Final: logits + log_softmax ----------------

__global__ void k_final(const float* __restrict__ Wl, const float* __restrict__ bl,
                        float* __restrict__ out) {
    __shared__ float sl[NGRAPH][10];
    __shared__ float sm[NGRAPH];
    __shared__ float ss[NGRAPH];
    int tid = threadIdx.x;                // 640 threads
    int g = tid / 10, c = tid % 10;
    if (tid < NGRAPH * 10) {
        float dot = bl[c];
        for (int k = 0; k < 128; k++) dot += d_pool[g * 128 + k] * Wl[k * 10 + c];
        sl[g][c] = dot;
    }
    __syncthreads();
    if (tid < NGRAPH) {
        float m = -1e30f;
        for (int j = 0; j < 10; j++) m = fmaxf(m, sl[tid][j]);
        float s = 0.f;
        for (int j = 0; j < 10; j++) s += expf(sl[tid][j] - m);
        sm[tid] = m; ss[tid] = logf(s);
    }
    __syncthreads();
    if (tid < NGRAPH * 10) out[tid] = sl[g][c] - sm[g] - ss[g];
}

// ---------------- Launch ----------------

extern "C" void kernel_launch(void* const* d_in, const int* in_sizes, int n_in,
                              void* d_out, int out_size) {
    (void)n_in; (void)out_size;
    const float* x     = (const float*)d_in[0];
    const void*  ei    = d_in[1];
    const void*  batch = d_in[2];
    const float* W1    = (const float*)d_in[3];
    const float* b1    = (const float*)d_in[4];
    const float* W2    = (const float*)d_in[5];
    const float* b2    = (const float*)d_in[6];
    const float* Wl    = (const float*)d_in[7];
    const float* bl    = (const float*)d_in[8];
    float* out = (float*)d_out;

    int N = in_sizes[0] / HDIM;
    int E = in_sizes[1] / 2;
    int nb = (N + 1023) >> 10;

    // dtype probe: first 4096 32-bit words of edge_index (safe for either dtype)
    k_detect<<<1, 256>>>((const unsigned int*)ei, 4096);

    k_init <<<(N + 255) / 256, 256>>>(N);
    k_count<<<(E + 255) / 256, 256>>>(ei, E);
    k_scan1<<<nb, 1024>>>(N);
    k_scan2<<<1, 32>>>(nb, N);
    k_scan3<<<(N + 255) / 256, 256>>>(N);
    k_csrfill<<<(E + N + 255) / 256, 256>>>(ei, E, N);

    // conv1: gemm (x @ W1, row-scaled by dinv) -> bufA; aggregate -> bufB (+b1, relu)
    k_gemm<<<(N + 63) / 64, 256>>>(x, 0, W1, N);
    k_agg<true><<<((long long)N * 32 + 255) / 256, 256>>>(b1, N);

    // conv2: gemm (bufB @ W2, row-scaled) -> bufA; aggregate -> bufB (+b2)
    k_gemm<<<(N + 63) / 64, 256>>>(nullptr, 2, W2, N);
    k_agg<false><<<((long long)N * 32 + 255) / 256, 256>>>(b2, N);

    // pool + classifier
    k_pool<<<NGRAPH, HDIM>>>(batch, N);
    k_final<<<1, 640>>>(Wl, bl, out);
}